// round 15
// baseline (speedup 1.0000x reference)
#include <cuda_runtime.h>
#include <cuda_fp16.h>

#define NN 100000
#define F1 128
#define F2 64
#define F3 40
#define EMAX 1700000
#define NB 391  // ceil(NN/256)

// ---------------- scratch ---------------------------------------------------
__device__ int   g_deg[NN];
__device__ float g_dis[NN];
__device__ int   g_off[NN + 1];
__device__ int   g_cur[NN];
__device__ int   g_bsum[512];
__device__ int   g_csr[EMAX];
__device__ __align__(16) __half g_xh[NN * F2];  // (x@W1)*dis in fp16, [r][64]
__device__ __align__(16) float  g_h[NN * F2];   // relu out fp32, [r][64]
__device__ __align__(16) float  g_hwf[NN * F3]; // (h@W2)*dis fp32, [r][40]
__device__ int g_is64;

// ---------------- fp16 pack/unpack helpers ----------------------------------
union H2U { __half2 h; unsigned u; };

__device__ __forceinline__ unsigned pack_h2(float a, float b) {
    H2U t; t.h = __floats2half2_rn(a, b); return t.u;
}
__device__ __forceinline__ float2 unpack_h2(unsigned u) {
    H2U t; t.u = u; return __half22float2(t.h);
}
__device__ __forceinline__ void acc8(float* a, uint4 u) {
    float2 f0 = unpack_h2(u.x);
    float2 f1 = unpack_h2(u.y);
    float2 f2 = unpack_h2(u.z);
    float2 f3 = unpack_h2(u.w);
    a[0] += f0.x; a[1] += f0.y; a[2] += f1.x; a[3] += f1.y;
    a[4] += f2.x; a[5] += f2.y; a[6] += f3.x; a[7] += f3.y;
}

// ---------------- edge index fetch (dtype-agnostic) -------------------------
__device__ __forceinline__ int edge_idx(const void* ei, long long E,
                                        long long e, int which) {
    if (g_is64) return (int)((const long long*)ei)[(long long)which * E + e];
    return ((const int*)ei)[(long long)which * E + e];
}

// ---------------- init: dtype probe + zero degree ---------------------------
__global__ void k_init(const int* __restrict__ ei) {
    int i = blockIdx.x * blockDim.x + threadIdx.x;
    if (i < NN) g_deg[i] = 0;
    if (i == 0) {
        int ones = 0;
        for (int j = 0; j < 256; j++) ones |= ei[2 * j + 1];
        g_is64 = (ones == 0) ? 1 : 0;
    }
}

__global__ void k_deg(const void* __restrict__ ei, int E) {
    int i = blockIdx.x * blockDim.x + threadIdx.x;
    if (i >= E) return;
    int d = edge_idx(ei, E, i, 1);
    if ((unsigned)d < NN) atomicAdd(&g_deg[d], 1);
}

// ---------------- dis + scan step 1 -----------------------------------------
__global__ void k_dis_scan1() {
    __shared__ int wsum[8];
    int i = blockIdx.x * 256 + threadIdx.x;
    int lane = threadIdx.x & 31, w = threadIdx.x >> 5;
    int deg = (i < NN) ? g_deg[i] : 0;
    if (i < NN) g_dis[i] = rsqrtf((float)(deg + 1));
    int incl = deg;
    #pragma unroll
    for (int o = 1; o < 32; o <<= 1) {
        int t = __shfl_up_sync(0xffffffffu, incl, o);
        if (lane >= o) incl += t;
    }
    if (lane == 31) wsum[w] = incl;
    __syncthreads();
    if (w == 0) {
        int s = (lane < 8) ? wsum[lane] : 0;
        #pragma unroll
        for (int o = 1; o < 8; o <<= 1) {
            int t = __shfl_up_sync(0xffffffffu, s, o);
            if (lane >= o) s += t;
        }
        if (lane < 8) wsum[lane] = s;
    }
    __syncthreads();
    if (w > 0) incl += wsum[w - 1];
    if (i < NN) g_off[i + 1] = incl;
    if (threadIdx.x == 255) g_bsum[blockIdx.x] = incl;
}

__global__ void k_scan2() {
    __shared__ int s[512];
    int t = threadIdx.x;
    s[t] = (t < NB) ? g_bsum[t] : 0;
    __syncthreads();
    for (int o = 1; o < 512; o <<= 1) {
        int v = (t >= o) ? s[t - o] : 0;
        __syncthreads();
        s[t] += v;
        __syncthreads();
    }
    if (t < NB) g_bsum[t] = (t > 0) ? s[t - 1] : 0;
}

__global__ void k_scan3() {
    int j = blockIdx.x * blockDim.x + threadIdx.x;
    if (j > NN) return;
    int v = (j == 0) ? 0 : g_off[j] + g_bsum[(j - 1) >> 8];
    g_off[j] = v;
    if (j < NN) g_cur[j] = v;
}

__global__ void k_fill(const void* __restrict__ ei, int E) {
    int e = blockIdx.x * blockDim.x + threadIdx.x;
    if (e >= E) return;
    int s = edge_idx(ei, E, e, 0);
    int d = edge_idx(ei, E, e, 1);
    if ((unsigned)s >= NN || (unsigned)d >= NN) return;
    int pos = atomicAdd(&g_cur[d], 1);
    if (pos < EMAX) g_csr[pos] = s;
}

// ---------------- GEMM1: 128x64 block, 8x4 micro-tile (R10), fp16 out -------
__global__ void __launch_bounds__(256, 4)
k_gemm1(const float* __restrict__ X, const float* __restrict__ W) {
    __shared__ float Xs[16][128];  // [k][row]
    __shared__ float Ws[16][64];   // [k][col]
    int tid = threadIdx.x;
    int rbase = blockIdx.x * 128;
    int m0 = (tid >> 4) * 8;       // 0..120
    int n0 = (tid & 15) * 4;       // 0..60

    float c[8][4] = {};

    #pragma unroll 1
    for (int kc = 0; kc < F1; kc += 16) {
        #pragma unroll
        for (int it = 0; it < 2; it++) {
            int idx = tid + it * 256;
            int row = idx >> 2, q = idx & 3;
            int rr = min(rbase + row, NN - 1);
            float4 v = *(const float4*)(X + (size_t)rr * F1 + kc + q * 4);
            Xs[q * 4 + 0][row] = v.x;
            Xs[q * 4 + 1][row] = v.y;
            Xs[q * 4 + 2][row] = v.z;
            Xs[q * 4 + 3][row] = v.w;
        }
        {
            int k = tid >> 4, c4 = tid & 15;
            float4 v = *(const float4*)(W + (size_t)(kc + k) * F2 + c4 * 4);
            *(float4*)&Ws[k][c4 * 4] = v;
        }
        __syncthreads();
        #pragma unroll
        for (int k = 0; k < 16; k++) {
            float4 a0 = *(float4*)&Xs[k][m0];
            float4 a1 = *(float4*)&Xs[k][m0 + 4];
            float4 b  = *(float4*)&Ws[k][n0];
            float av[8] = {a0.x, a0.y, a0.z, a0.w, a1.x, a1.y, a1.z, a1.w};
            #pragma unroll
            for (int i = 0; i < 8; i++) {
                c[i][0] = fmaf(av[i], b.x, c[i][0]);
                c[i][1] = fmaf(av[i], b.y, c[i][1]);
                c[i][2] = fmaf(av[i], b.z, c[i][2]);
                c[i][3] = fmaf(av[i], b.w, c[i][3]);
            }
        }
        __syncthreads();
    }

    #pragma unroll
    for (int i = 0; i < 8; i++) {
        int r = rbase + m0 + i;
        if (r < NN) {
            float d = g_dis[r];
            uint2 packed = make_uint2(pack_h2(c[i][0] * d, c[i][1] * d),
                                      pack_h2(c[i][2] * d, c[i][3] * d));
            *(uint2*)(g_xh + (size_t)r * F2 + n0) = packed;
        }
    }
}

// ---------------- agg1: fp16 gather, uniform stride-16 loop -----------------
// 8 lanes per edge (128B row), 4 edge-groups per warp, 4 predicated LDG waves.
__global__ void k_agg1(const float* __restrict__ b1) {
    int lane = threadIdx.x & 31;
    int c8 = lane & 7;      // 16B chunk within 128B row
    int g  = lane >> 3;     // edge group 0..3
    int n = blockIdx.x * 8 + (threadIdx.x >> 5);
    if (n >= NN) return;
    int beg = g_off[n], end = g_off[n + 1];
    const uint4* xh4 = (const uint4*)g_xh;  // 8 uint4 per row

    float aA[8] = {}, aB[8] = {}, aC[8] = {}, aD[8] = {};
    if (g == 3) acc8(aA, xh4[(size_t)n * 8 + c8]);  // self-loop in group 3

    for (int base = beg; base < end; base += 32) {
        int cnt = min(32, end - base);  // warp-uniform
        int sl = (lane < cnt) ? g_csr[base + lane] : 0;
        // warp-uniform trip count; all shuffles executed by all 32 lanes
        for (int k = 0; k < cnt; k += 16) {
            int iA = k + g, iB = k + 4 + g, iC = k + 8 + g, iD = k + 12 + g;
            int sA = __shfl_sync(0xffffffffu, sl, iA < cnt ? iA : 0);
            int sB = __shfl_sync(0xffffffffu, sl, iB < cnt ? iB : 0);
            int sC = __shfl_sync(0xffffffffu, sl, iC < cnt ? iC : 0);
            int sD = __shfl_sync(0xffffffffu, sl, iD < cnt ? iD : 0);
            if (iA < cnt) acc8(aA, xh4[(size_t)sA * 8 + c8]);
            if (iB < cnt) acc8(aB, xh4[(size_t)sB * 8 + c8]);
            if (iC < cnt) acc8(aC, xh4[(size_t)sC * 8 + c8]);
            if (iD < cnt) acc8(aD, xh4[(size_t)sD * 8 + c8]);
        }
    }

    float a[8];
    #pragma unroll
    for (int j = 0; j < 8; j++) {
        a[j] = (aA[j] + aB[j]) + (aC[j] + aD[j]);
        a[j] += __shfl_xor_sync(0xffffffffu, a[j], 8);
        a[j] += __shfl_xor_sync(0xffffffffu, a[j], 16);
    }

    if (g == 0) {  // lanes 0..7 write 8 floats each
        float d = g_dis[n];
        float4 b0 = *(const float4*)(b1 + c8 * 8);
        float4 b1v = *(const float4*)(b1 + c8 * 8 + 4);
        float4 o0 = make_float4(fmaxf(d * a[0] + b0.x, 0.f),
                                fmaxf(d * a[1] + b0.y, 0.f),
                                fmaxf(d * a[2] + b0.z, 0.f),
                                fmaxf(d * a[3] + b0.w, 0.f));
        float4 o1 = make_float4(fmaxf(d * a[4] + b1v.x, 0.f),
                                fmaxf(d * a[5] + b1v.y, 0.f),
                                fmaxf(d * a[6] + b1v.z, 0.f),
                                fmaxf(d * a[7] + b1v.w, 0.f));
        *(float4*)(g_h + (size_t)n * F2 + c8 * 8) = o0;
        *(float4*)(g_h + (size_t)n * F2 + c8 * 8 + 4) = o1;
    }
}

// ---------------- GEMM2: 128x40 block, 8x4 micro-tile, 160 thr (R10) --------
__global__ void k_gemm2(const float* __restrict__ W) {
    __shared__ float Xs[16][128];  // [k][row]
    __shared__ float Ws[16][40];   // [k][col]
    int tid = threadIdx.x;
    int rbase = blockIdx.x * 128;
    int m0 = (tid / 10) * 8;
    int n0 = (tid % 10) * 4;

    float c[8][4] = {};

    #pragma unroll 1
    for (int kc = 0; kc < F2; kc += 16) {
        for (int idx = tid; idx < 512; idx += 160) {
            int row = idx >> 2, q = idx & 3;
            int rr = min(rbase + row, NN - 1);
            float4 v = *(const float4*)(g_h + (size_t)rr * F2 + kc + q * 4);
            Xs[q * 4 + 0][row] = v.x;
            Xs[q * 4 + 1][row] = v.y;
            Xs[q * 4 + 2][row] = v.z;
            Xs[q * 4 + 3][row] = v.w;
        }
        {
            int k = tid / 10, c4 = tid % 10;
            float4 v = *(const float4*)(W + (size_t)(kc + k) * F3 + c4 * 4);
            *(float4*)&Ws[k][c4 * 4] = v;
        }
        __syncthreads();
        #pragma unroll
        for (int k = 0; k < 16; k++) {
            float4 a0 = *(float4*)&Xs[k][m0];
            float4 a1 = *(float4*)&Xs[k][m0 + 4];
            float4 b  = *(float4*)&Ws[k][n0];
            float av[8] = {a0.x, a0.y, a0.z, a0.w, a1.x, a1.y, a1.z, a1.w};
            #pragma unroll
            for (int i = 0; i < 8; i++) {
                c[i][0] = fmaf(av[i], b.x, c[i][0]);
                c[i][1] = fmaf(av[i], b.y, c[i][1]);
                c[i][2] = fmaf(av[i], b.z, c[i][2]);
                c[i][3] = fmaf(av[i], b.w, c[i][3]);
            }
        }
        __syncthreads();
    }

    #pragma unroll
    for (int i = 0; i < 8; i++) {
        int r = rbase + m0 + i;
        if (r < NN) {
            float d = g_dis[r];
            float4 o = make_float4(c[i][0] * d, c[i][1] * d, c[i][2] * d, c[i][3] * d);
            *(float4*)(g_hwf + (size_t)r * F3 + n0) = o;
        }
    }
}

// ---------------- agg2: float2 gather, 4 edges in flight + log-softmax ------
__global__ void k_agg2(const float* __restrict__ b2, float* __restrict__ out) {
    int lane = threadIdx.x & 31;
    int n = blockIdx.x * 8 + (threadIdx.x >> 5);
    if (n >= NN) return;
    bool act = lane < 20;
    const float2* hw2 = (const float2*)g_hwf;  // 20 per row
    int beg = g_off[n], end = g_off[n + 1];

    float2 aA = make_float2(0.f, 0.f), aB = make_float2(0.f, 0.f);
    float2 aC = make_float2(0.f, 0.f), aD = make_float2(0.f, 0.f);
    if (act) aA = hw2[(size_t)n * 20 + lane];  // self-loop

    for (int base = beg; base < end; base += 32) {
        int cnt = min(32, end - base);
        int sl = (lane < cnt) ? g_csr[base + lane] : 0;
        int k = 0;
        for (; k + 3 < cnt; k += 4) {
            int s0 = __shfl_sync(0xffffffffu, sl, k);
            int s1 = __shfl_sync(0xffffffffu, sl, k + 1);
            int s2 = __shfl_sync(0xffffffffu, sl, k + 2);
            int s3 = __shfl_sync(0xffffffffu, sl, k + 3);
            if (act) {
                float2 v0 = hw2[(size_t)s0 * 20 + lane];
                float2 v1 = hw2[(size_t)s1 * 20 + lane];
                float2 v2 = hw2[(size_t)s2 * 20 + lane];
                float2 v3 = hw2[(size_t)s3 * 20 + lane];
                aA.x += v0.x; aA.y += v0.y;
                aB.x += v1.x; aB.y += v1.y;
                aC.x += v2.x; aC.y += v2.y;
                aD.x += v3.x; aD.y += v3.y;
            }
        }
        for (; k < cnt; k++) {
            int s0 = __shfl_sync(0xffffffffu, sl, k);
            if (act) {
                float2 v = hw2[(size_t)s0 * 20 + lane];
                aA.x += v.x; aA.y += v.y;
            }
        }
    }

    float d = g_dis[n];
    float sx = aA.x + aB.x + aC.x + aD.x;
    float sy = aA.y + aB.y + aC.y + aD.y;
    float zx = act ? d * sx + b2[2 * lane]     : -3.4e38f;
    float zy = act ? d * sy + b2[2 * lane + 1] : -3.4e38f;

    float m = fmaxf(zx, zy);
    #pragma unroll
    for (int o = 16; o; o >>= 1) m = fmaxf(m, __shfl_xor_sync(0xffffffffu, m, o));
    float s = act ? (expf(zx - m) + expf(zy - m)) : 0.f;
    #pragma unroll
    for (int o = 16; o; o >>= 1) s += __shfl_xor_sync(0xffffffffu, s, o);
    float lse = m + logf(s);

    if (act) {
        out[(size_t)n * F3 + 2 * lane]     = zx - lse;
        out[(size_t)n * F3 + 2 * lane + 1] = zy - lse;
    }
}

// ---------------- launcher --------------------------------------------------
extern "C" void kernel_launch(void* const* d_in, const int* in_sizes, int n_in,
                              void* d_out, int out_size) {
    const float* x  = (const float*)d_in[0];
    const void*  ei = d_in[1];
    const float* W1 = (const float*)d_in[2];
    const float* b1 = (const float*)d_in[3];
    const float* W2 = (const float*)d_in[4];
    const float* b2 = (const float*)d_in[5];
    float* out = (float*)d_out;

    int E = in_sizes[1] / 2;
    int eb = (E + 255) / 256;

    static cudaStream_t s2 = 0;
    static cudaEvent_t evA = 0, evB = 0;
    if (!s2) {
        cudaStreamCreateWithFlags(&s2, cudaStreamNonBlocking);
        cudaEventCreateWithFlags(&evA, cudaEventDisableTiming);
        cudaEventCreateWithFlags(&evB, cudaEventDisableTiming);
    }

    k_init<<<NB, 256>>>((const int*)ei);
    k_deg<<<eb, 256>>>(ei, E);
    k_dis_scan1<<<NB, 256>>>();

    // fork: gemm1 (needs x, W1, dis) overlaps the CSR build
    cudaEventRecord(evA, 0);
    cudaStreamWaitEvent(s2, evA, 0);
    k_gemm1<<<(NN + 127) / 128, 256, 0, s2>>>(x, W1);
    cudaEventRecord(evB, s2);

    k_scan2<<<1, 512>>>();
    k_scan3<<<(NN + 256) / 256, 256>>>();
    k_fill<<<eb, 256>>>(ei, E);

    cudaStreamWaitEvent(0, evB, 0);  // join before agg1

    k_agg1<<<(NN + 7) / 8, 256>>>(b1);
    k_gemm2<<<(NN + 127) / 128, 160>>>(W2);
    k_agg2<<<(NN + 7) / 8, 256>>>(b2, out);
}

// round 16
// speedup vs baseline: 1.1174x; 1.1174x over previous
#include <cuda_runtime.h>

#define NN 100000
#define F1 128
#define F2 64
#define F3 40
#define EMAX 1700000
#define NB 391  // ceil(NN/256)

// ---------------- scratch ---------------------------------------------------
__device__ int   g_deg[NN];
__device__ float g_dis[NN];
__device__ int   g_off[NN + 1];
__device__ int   g_cur[NN];
__device__ int   g_bsum[512];
__device__ int   g_csr[EMAX];
__device__ __align__(16) float g_xws[NN * F2];  // x@W1 then *dis, [r][64]
__device__ __align__(16) float g_h[NN * F2];    // relu out, [r][64]
__device__ __align__(16) float g_hwf[NN * F3];  // (h@W2)*dis, [r][40]
__device__ int g_is64;

// ---------------- edge index fetch (dtype-agnostic) -------------------------
__device__ __forceinline__ int edge_idx(const void* ei, long long E,
                                        long long e, int which) {
    if (g_is64) return (int)((const long long*)ei)[(long long)which * E + e];
    return ((const int*)ei)[(long long)which * E + e];
}

// ---------------- init: dtype probe + zero degree ---------------------------
__global__ void k_init(const int* __restrict__ ei) {
    int i = blockIdx.x * blockDim.x + threadIdx.x;
    if (i < NN) g_deg[i] = 0;
    if (i == 0) {
        int ones = 0;
        for (int j = 0; j < 256; j++) ones |= ei[2 * j + 1];
        g_is64 = (ones == 0) ? 1 : 0;
    }
}

__global__ void k_deg(const void* __restrict__ ei, int E) {
    int i = blockIdx.x * blockDim.x + threadIdx.x;
    if (i >= E) return;
    int d = edge_idx(ei, E, i, 1);
    if ((unsigned)d < NN) atomicAdd(&g_deg[d], 1);
}

// ---------------- dis + scan step 1 -----------------------------------------
__global__ void k_dis_scan1() {
    __shared__ int wsum[8];
    int i = blockIdx.x * 256 + threadIdx.x;
    int lane = threadIdx.x & 31, w = threadIdx.x >> 5;
    int deg = (i < NN) ? g_deg[i] : 0;
    if (i < NN) g_dis[i] = rsqrtf((float)(deg + 1));
    int incl = deg;
    #pragma unroll
    for (int o = 1; o < 32; o <<= 1) {
        int t = __shfl_up_sync(0xffffffffu, incl, o);
        if (lane >= o) incl += t;
    }
    if (lane == 31) wsum[w] = incl;
    __syncthreads();
    if (w == 0) {
        int s = (lane < 8) ? wsum[lane] : 0;
        #pragma unroll
        for (int o = 1; o < 8; o <<= 1) {
            int t = __shfl_up_sync(0xffffffffu, s, o);
            if (lane >= o) s += t;
        }
        if (lane < 8) wsum[lane] = s;
    }
    __syncthreads();
    if (w > 0) incl += wsum[w - 1];
    if (i < NN) g_off[i + 1] = incl;
    if (threadIdx.x == 255) g_bsum[blockIdx.x] = incl;
}

__global__ void k_scan2() {
    __shared__ int s[512];
    int t = threadIdx.x;
    s[t] = (t < NB) ? g_bsum[t] : 0;
    __syncthreads();
    for (int o = 1; o < 512; o <<= 1) {
        int v = (t >= o) ? s[t - o] : 0;
        __syncthreads();
        s[t] += v;
        __syncthreads();
    }
    if (t < NB) g_bsum[t] = (t > 0) ? s[t - 1] : 0;
}

__global__ void k_scan3() {
    int j = blockIdx.x * blockDim.x + threadIdx.x;
    if (j > NN) return;
    int v = (j == 0) ? 0 : g_off[j] + g_bsum[(j - 1) >> 8];
    g_off[j] = v;
    if (j < NN) g_cur[j] = v;
}

__global__ void k_fill(const void* __restrict__ ei, int E) {
    int e = blockIdx.x * blockDim.x + threadIdx.x;
    if (e >= E) return;
    int s = edge_idx(ei, E, e, 0);
    int d = edge_idx(ei, E, e, 1);
    if ((unsigned)s >= NN || (unsigned)d >= NN) return;
    int pos = atomicAdd(&g_cur[d], 1);
    if (pos < EMAX) g_csr[pos] = s;
}

// ---------------- GEMM1: 128x64 block, 8x4 micro-tile (R10), RAW out --------
__global__ void __launch_bounds__(256, 4)
k_gemm1(const float* __restrict__ X, const float* __restrict__ W) {
    __shared__ float Xs[16][128];  // [k][row]
    __shared__ float Ws[16][64];   // [k][col]
    int tid = threadIdx.x;
    int rbase = blockIdx.x * 128;
    int m0 = (tid >> 4) * 8;       // 0..120
    int n0 = (tid & 15) * 4;       // 0..60

    float c[8][4] = {};

    #pragma unroll 1
    for (int kc = 0; kc < F1; kc += 16) {
        #pragma unroll
        for (int it = 0; it < 2; it++) {
            int idx = tid + it * 256;
            int row = idx >> 2, q = idx & 3;
            int rr = min(rbase + row, NN - 1);
            float4 v = *(const float4*)(X + (size_t)rr * F1 + kc + q * 4);
            Xs[q * 4 + 0][row] = v.x;
            Xs[q * 4 + 1][row] = v.y;
            Xs[q * 4 + 2][row] = v.z;
            Xs[q * 4 + 3][row] = v.w;
        }
        {
            int k = tid >> 4, c4 = tid & 15;
            float4 v = *(const float4*)(W + (size_t)(kc + k) * F2 + c4 * 4);
            *(float4*)&Ws[k][c4 * 4] = v;
        }
        __syncthreads();
        #pragma unroll
        for (int k = 0; k < 16; k++) {
            float4 a0 = *(float4*)&Xs[k][m0];
            float4 a1 = *(float4*)&Xs[k][m0 + 4];
            float4 b  = *(float4*)&Ws[k][n0];
            float av[8] = {a0.x, a0.y, a0.z, a0.w, a1.x, a1.y, a1.z, a1.w};
            #pragma unroll
            for (int i = 0; i < 8; i++) {
                c[i][0] = fmaf(av[i], b.x, c[i][0]);
                c[i][1] = fmaf(av[i], b.y, c[i][1]);
                c[i][2] = fmaf(av[i], b.z, c[i][2]);
                c[i][3] = fmaf(av[i], b.w, c[i][3]);
            }
        }
        __syncthreads();
    }

    #pragma unroll
    for (int i = 0; i < 8; i++) {
        int r = rbase + m0 + i;
        if (r < NN) {
            float4 o = make_float4(c[i][0], c[i][1], c[i][2], c[i][3]);
            *(float4*)(g_xws + (size_t)r * F2 + n0) = o;
        }
    }
}

// ---------------- scale: xws[r][*] *= dis[r] (overlaps k_fill) --------------
__global__ void k_scale() {
    int i = blockIdx.x * blockDim.x + threadIdx.x;  // one float4 per thread
    if (i >= NN * (F2 / 4)) return;
    int r = i >> 4;
    float d = g_dis[r];
    float4* p = (float4*)g_xws + i;
    float4 v = *p;
    *p = make_float4(v.x * d, v.y * d, v.z * d, v.w * d);
}

// ---------------- agg1: float4 gather, 8 edges / 4 LDG-waves (R10) ----------
__global__ void k_agg1(const float* __restrict__ b1) {
    int lane = threadIdx.x & 31;
    int c4 = lane & 15;     // float4 chunk
    int half = lane >> 4;   // 0 or 1
    int n = blockIdx.x * 8 + (threadIdx.x >> 5);
    if (n >= NN) return;
    int beg = g_off[n], end = g_off[n + 1];
    const float4* xws4 = (const float4*)g_xws;

    float4 aA = make_float4(0.f, 0.f, 0.f, 0.f);
    float4 aB = make_float4(0.f, 0.f, 0.f, 0.f);
    float4 aC = make_float4(0.f, 0.f, 0.f, 0.f);
    float4 aD = make_float4(0.f, 0.f, 0.f, 0.f);
    if (half == 1) aA = xws4[(size_t)n * 16 + c4];  // self-loop

    for (int base = beg; base < end; base += 32) {
        int cnt = min(32, end - base);
        int sl = (lane < cnt) ? g_csr[base + lane] : 0;
        int k = 0;
        for (; k + 7 < cnt; k += 8) {
            int sA = __shfl_sync(0xffffffffu, sl, k + half);
            int sB = __shfl_sync(0xffffffffu, sl, k + 2 + half);
            int sC = __shfl_sync(0xffffffffu, sl, k + 4 + half);
            int sD = __shfl_sync(0xffffffffu, sl, k + 6 + half);
            float4 vA = xws4[(size_t)sA * 16 + c4];
            float4 vB = xws4[(size_t)sB * 16 + c4];
            float4 vC = xws4[(size_t)sC * 16 + c4];
            float4 vD = xws4[(size_t)sD * 16 + c4];
            aA.x += vA.x; aA.y += vA.y; aA.z += vA.z; aA.w += vA.w;
            aB.x += vB.x; aB.y += vB.y; aB.z += vB.z; aB.w += vB.w;
            aC.x += vC.x; aC.y += vC.y; aC.z += vC.z; aC.w += vC.w;
            aD.x += vD.x; aD.y += vD.y; aD.z += vD.z; aD.w += vD.w;
        }
        for (; k + 1 < cnt; k += 2) {
            int s = __shfl_sync(0xffffffffu, sl, k + half);
            float4 v = xws4[(size_t)s * 16 + c4];
            aA.x += v.x; aA.y += v.y; aA.z += v.z; aA.w += v.w;
        }
        if (k < cnt) {
            int s = __shfl_sync(0xffffffffu, sl, k);
            if (half == 0) {
                float4 v = xws4[(size_t)s * 16 + c4];
                aA.x += v.x; aA.y += v.y; aA.z += v.z; aA.w += v.w;
            }
        }
    }
    float4 acc = make_float4(aA.x + aB.x + aC.x + aD.x,
                             aA.y + aB.y + aC.y + aD.y,
                             aA.z + aB.z + aC.z + aD.z,
                             aA.w + aB.w + aC.w + aD.w);
    acc.x += __shfl_xor_sync(0xffffffffu, acc.x, 16);
    acc.y += __shfl_xor_sync(0xffffffffu, acc.y, 16);
    acc.z += __shfl_xor_sync(0xffffffffu, acc.z, 16);
    acc.w += __shfl_xor_sync(0xffffffffu, acc.w, 16);

    if (half == 0) {
        float d = g_dis[n];
        float4 bb = *(const float4*)(b1 + c4 * 4);
        float4 o = make_float4(fmaxf(d * acc.x + bb.x, 0.f),
                               fmaxf(d * acc.y + bb.y, 0.f),
                               fmaxf(d * acc.z + bb.z, 0.f),
                               fmaxf(d * acc.w + bb.w, 0.f));
        *(float4*)(g_h + (size_t)n * F2 + c4 * 4) = o;
    }
}

// ---------------- GEMM2: 128x40 block, 8x4 micro-tile, 160 thr (R10) --------
__global__ void k_gemm2(const float* __restrict__ W) {
    __shared__ float Xs[16][128];  // [k][row]
    __shared__ float Ws[16][40];   // [k][col]
    int tid = threadIdx.x;
    int rbase = blockIdx.x * 128;
    int m0 = (tid / 10) * 8;
    int n0 = (tid % 10) * 4;

    float c[8][4] = {};

    #pragma unroll 1
    for (int kc = 0; kc < F2; kc += 16) {
        for (int idx = tid; idx < 512; idx += 160) {
            int row = idx >> 2, q = idx & 3;
            int rr = min(rbase + row, NN - 1);
            float4 v = *(const float4*)(g_h + (size_t)rr * F2 + kc + q * 4);
            Xs[q * 4 + 0][row] = v.x;
            Xs[q * 4 + 1][row] = v.y;
            Xs[q * 4 + 2][row] = v.z;
            Xs[q * 4 + 3][row] = v.w;
        }
        {
            int k = tid / 10, c4 = tid % 10;
            float4 v = *(const float4*)(W + (size_t)(kc + k) * F3 + c4 * 4);
            *(float4*)&Ws[k][c4 * 4] = v;
        }
        __syncthreads();
        #pragma unroll
        for (int k = 0; k < 16; k++) {
            float4 a0 = *(float4*)&Xs[k][m0];
            float4 a1 = *(float4*)&Xs[k][m0 + 4];
            float4 b  = *(float4*)&Ws[k][n0];
            float av[8] = {a0.x, a0.y, a0.z, a0.w, a1.x, a1.y, a1.z, a1.w};
            #pragma unroll
            for (int i = 0; i < 8; i++) {
                c[i][0] = fmaf(av[i], b.x, c[i][0]);
                c[i][1] = fmaf(av[i], b.y, c[i][1]);
                c[i][2] = fmaf(av[i], b.z, c[i][2]);
                c[i][3] = fmaf(av[i], b.w, c[i][3]);
            }
        }
        __syncthreads();
    }

    #pragma unroll
    for (int i = 0; i < 8; i++) {
        int r = rbase + m0 + i;
        if (r < NN) {
            float d = g_dis[r];
            float4 o = make_float4(c[i][0] * d, c[i][1] * d, c[i][2] * d, c[i][3] * d);
            *(float4*)(g_hwf + (size_t)r * F3 + n0) = o;
        }
    }
}

// ---------------- agg2: float2 gather, 4 edges in flight + log-softmax ------
__global__ void k_agg2(const float* __restrict__ b2, float* __restrict__ out) {
    int lane = threadIdx.x & 31;
    int n = blockIdx.x * 8 + (threadIdx.x >> 5);
    if (n >= NN) return;
    bool act = lane < 20;
    const float2* hw2 = (const float2*)g_hwf;  // 20 per row
    int beg = g_off[n], end = g_off[n + 1];

    float2 aA = make_float2(0.f, 0.f), aB = make_float2(0.f, 0.f);
    float2 aC = make_float2(0.f, 0.f), aD = make_float2(0.f, 0.f);
    if (act) aA = hw2[(size_t)n * 20 + lane];  // self-loop

    for (int base = beg; base < end; base += 32) {
        int cnt = min(32, end - base);
        int sl = (lane < cnt) ? g_csr[base + lane] : 0;
        int k = 0;
        for (; k + 3 < cnt; k += 4) {
            int s0 = __shfl_sync(0xffffffffu, sl, k);
            int s1 = __shfl_sync(0xffffffffu, sl, k + 1);
            int s2 = __shfl_sync(0xffffffffu, sl, k + 2);
            int s3 = __shfl_sync(0xffffffffu, sl, k + 3);
            if (act) {
                float2 v0 = hw2[(size_t)s0 * 20 + lane];
                float2 v1 = hw2[(size_t)s1 * 20 + lane];
                float2 v2 = hw2[(size_t)s2 * 20 + lane];
                float2 v3 = hw2[(size_t)s3 * 20 + lane];
                aA.x += v0.x; aA.y += v0.y;
                aB.x += v1.x; aB.y += v1.y;
                aC.x += v2.x; aC.y += v2.y;
                aD.x += v3.x; aD.y += v3.y;
            }
        }
        for (; k < cnt; k++) {
            int s0 = __shfl_sync(0xffffffffu, sl, k);
            if (act) {
                float2 v = hw2[(size_t)s0 * 20 + lane];
                aA.x += v.x; aA.y += v.y;
            }
        }
    }

    float d = g_dis[n];
    float sx = aA.x + aB.x + aC.x + aD.x;
    float sy = aA.y + aB.y + aC.y + aD.y;
    float zx = act ? d * sx + b2[2 * lane]     : -3.4e38f;
    float zy = act ? d * sy + b2[2 * lane + 1] : -3.4e38f;

    float m = fmaxf(zx, zy);
    #pragma unroll
    for (int o = 16; o; o >>= 1) m = fmaxf(m, __shfl_xor_sync(0xffffffffu, m, o));
    float s = act ? (expf(zx - m) + expf(zy - m)) : 0.f;
    #pragma unroll
    for (int o = 16; o; o >>= 1) s += __shfl_xor_sync(0xffffffffu, s, o);
    float lse = m + logf(s);

    if (act) {
        out[(size_t)n * F3 + 2 * lane]     = zx - lse;
        out[(size_t)n * F3 + 2 * lane + 1] = zy - lse;
    }
}

// ---------------- launcher --------------------------------------------------
extern "C" void kernel_launch(void* const* d_in, const int* in_sizes, int n_in,
                              void* d_out, int out_size) {
    const float* x  = (const float*)d_in[0];
    const void*  ei = d_in[1];
    const float* W1 = (const float*)d_in[2];
    const float* b1 = (const float*)d_in[3];
    const float* W2 = (const float*)d_in[4];
    const float* b2 = (const float*)d_in[5];
    float* out = (float*)d_out;

    int E = in_sizes[1] / 2;
    int eb = (E + 255) / 256;

    static cudaStream_t s2 = 0;
    static cudaEvent_t evA = 0, evB = 0, evDis = 0;
    if (!s2) {
        cudaStreamCreateWithFlags(&s2, cudaStreamNonBlocking);
        cudaEventCreateWithFlags(&evA, cudaEventDisableTiming);
        cudaEventCreateWithFlags(&evB, cudaEventDisableTiming);
        cudaEventCreateWithFlags(&evDis, cudaEventDisableTiming);
    }

    // fork at t=0: gemm1 needs only x/W1 (raw output, dis applied later)
    cudaEventRecord(evA, 0);
    cudaStreamWaitEvent(s2, evA, 0);
    k_gemm1<<<(NN + 127) / 128, 256, 0, s2>>>(x, W1);

    // prep chain on main stream, overlapped with gemm1
    k_init<<<NB, 256>>>((const int*)ei);
    k_deg<<<eb, 256>>>(ei, E);
    k_dis_scan1<<<NB, 256>>>();
    cudaEventRecord(evDis, 0);        // dis ready

    // scale on s2 after gemm1 (stream order) AND dis (event)
    cudaStreamWaitEvent(s2, evDis, 0);
    k_scale<<<(NN * (F2 / 4) + 255) / 256, 256, 0, s2>>>();
    cudaEventRecord(evB, s2);

    k_scan2<<<1, 512>>>();
    k_scan3<<<(NN + 256) / 256, 256>>>();
    k_fill<<<eb, 256>>>(ei, E);

    cudaStreamWaitEvent(0, evB, 0);   // join before agg1

    k_agg1<<<(NN + 7) / 8, 256>>>(b1);
    k_gemm2<<<(NN + 127) / 128, 160>>>(W2);
    k_agg2<<<(NN + 7) / 8, 256>>>(b2, out);
}